// round 7
// baseline (speedup 1.0000x reference)
#include <cuda_runtime.h>

typedef unsigned long long ULL;

#define Bn    8192
#define Hn    256
#define Pn    72
#define G3    768
#define INn   328
#define MLPn  256
#define BM    64
#define NTHR  512
#define SSTR  68            // floats; 68*4=272B, 16B-aligned rows, quad-stride 17 (odd)
#define NBLK  128           // 8192/64 exact

// ---------------- persistent device scratch (no allocations allowed) -------
// Transposed + lane-duplicated weights: g[k][2c] = g[k][2c+1] = W[c][k].
// One LDG.128 then yields two ready f32x2 multiplier operands (no pack MOVs).
// +2 pad rows so the 2-deep prefetch never faults.
__device__ float g_WihT[(INn + 2) * G3 * 2];
__device__ float g_WhhT[(Hn + 2) * G3 * 2];
__device__ float g_W1T [(Hn + 2) * MLPn * 2];
__device__ float g_W2T [(MLPn + 2) * Pn * 2];
__device__ float g_giT [(size_t)NBLK * G3 * BM];   // per-CTA [col][row] gi_text (+biases)

// ---------------- f32x2 packed helpers (FFMA2 = 128 FMA/cyc/SM) ------------
static __device__ __forceinline__ ULL pack2(float lo, float hi) {
    ULL r; asm("mov.b64 %0, {%1, %2};" : "=l"(r) : "f"(lo), "f"(hi)); return r;
}
static __device__ __forceinline__ void unpack2(ULL v, float& lo, float& hi) {
    asm("mov.b64 {%0, %1}, %2;" : "=f"(lo), "=f"(hi) : "l"(v));
}
static __device__ __forceinline__ ULL fma2(ULL a, ULL b, ULL c) {
    ULL d; asm("fma.rn.f32x2 %0, %1, %2, %3;" : "=l"(d) : "l"(a), "l"(b), "l"(c)); return d;
}

static __device__ __forceinline__ float fsigmoid(float x) {
    x = fminf(fmaxf(x, -30.f), 30.f);
    return __fdividef(1.f, 1.f + __expf(-x));
}
static __device__ __forceinline__ float ftanh(float x) {
    x = fminf(fmaxf(x, -15.f), 15.f);
    float e = __expf(-2.f * x);
    return __fdividef(1.f - e, 1.f + e);
}

// ---- dual-destination gemm on duplicated weights -------------------------
// accA += At·W[:,cA..cA+1], accB += At·W[:,cB..cB+1]
// At: smem k-major, stride SSTR; rows r0..r0+7 (two 16B quads, warp-broadcast).
// WA/WB: dup-layout weights, row stride WS floats, pre-offset to 2*col.
template<int K, int WS>
static __device__ __forceinline__ void gemm_dual(
    ULL (&accA)[4][2], ULL (&accB)[4][2],
    const float* At, int r0,
    const float* __restrict__ WA, const float* __restrict__ WB)
{
    ulonglong2 a0 = *reinterpret_cast<const ulonglong2*>(WA);
    ulonglong2 a1 = *reinterpret_cast<const ulonglong2*>(WA + WS);
    ulonglong2 b0 = *reinterpret_cast<const ulonglong2*>(WB);
    ulonglong2 b1 = *reinterpret_cast<const ulonglong2*>(WB + WS);
    #pragma unroll 4
    for (int k = 0; k < K; ++k) {
        ulonglong2 a2 = *reinterpret_cast<const ulonglong2*>(WA + (size_t)(k + 2) * WS);
        ulonglong2 b2 = *reinterpret_cast<const ulonglong2*>(WB + (size_t)(k + 2) * WS);
        ulonglong2 h01 = *reinterpret_cast<const ulonglong2*>(At + k * SSTR + r0);
        ulonglong2 h23 = *reinterpret_cast<const ulonglong2*>(At + k * SSTR + r0 + 4);
        ULL h[4] = {h01.x, h01.y, h23.x, h23.y};
        #pragma unroll
        for (int j = 0; j < 4; ++j) {
            accA[j][0] = fma2(h[j], a0.x, accA[j][0]);
            accA[j][1] = fma2(h[j], a0.y, accA[j][1]);
            accB[j][0] = fma2(h[j], b0.x, accB[j][0]);
            accB[j][1] = fma2(h[j], b0.y, accB[j][1]);
        }
        a0 = a1; a1 = a2; b0 = b1; b1 = b2;
    }
}

// single-destination variant (MLP2), dup weights
template<int K, int WS>
static __device__ __forceinline__ void gemm_one(
    ULL (&acc)[4][2], const float* At, int r0, const float* __restrict__ W)
{
    ulonglong2 a0 = *reinterpret_cast<const ulonglong2*>(W);
    ulonglong2 a1 = *reinterpret_cast<const ulonglong2*>(W + WS);
    #pragma unroll 4
    for (int k = 0; k < K; ++k) {
        ulonglong2 a2 = *reinterpret_cast<const ulonglong2*>(W + (size_t)(k + 2) * WS);
        ulonglong2 h01 = *reinterpret_cast<const ulonglong2*>(At + k * SSTR + r0);
        ulonglong2 h23 = *reinterpret_cast<const ulonglong2*>(At + k * SSTR + r0 + 4);
        ULL h[4] = {h01.x, h01.y, h23.x, h23.y};
        #pragma unroll
        for (int j = 0; j < 4; ++j) {
            acc[j][0] = fma2(h[j], a0.x, acc[j][0]);
            acc[j][1] = fma2(h[j], a0.y, acc[j][1]);
        }
        a0 = a1; a1 = a2;
    }
}

// ---------------- prep: transpose + duplicate weights -----------------------
__global__ __launch_bounds__(256)
void rtmg_prep(const float* __restrict__ W_ih, const float* __restrict__ W_hh,
               const float* __restrict__ W1,   const float* __restrict__ W2)
{
    const int idx = blockIdx.x * blockDim.x + threadIdx.x;
    const int stride = gridDim.x * blockDim.x;
    for (int i = idx; i < INn * G3; i += stride) {
        int k = i / G3, c = i % G3;
        float v = W_ih[c * INn + k];
        g_WihT[(size_t)k * (G3 * 2) + 2 * c]     = v;
        g_WihT[(size_t)k * (G3 * 2) + 2 * c + 1] = v;
    }
    for (int i = idx; i < Hn * G3; i += stride) {
        int k = i / G3, c = i % G3;
        float v = W_hh[c * Hn + k];
        g_WhhT[(size_t)k * (G3 * 2) + 2 * c]     = v;
        g_WhhT[(size_t)k * (G3 * 2) + 2 * c + 1] = v;
    }
    for (int i = idx; i < Hn * MLPn; i += stride) {
        int k = i / MLPn, c = i % MLPn;
        float v = W1[c * Hn + k];
        g_W1T[(size_t)k * (MLPn * 2) + 2 * c]     = v;
        g_W1T[(size_t)k * (MLPn * 2) + 2 * c + 1] = v;
    }
    for (int i = idx; i < MLPn * Pn; i += stride) {
        int k = i / Pn, c = i % Pn;
        float v = W2[c * MLPn + k];
        g_W2T[(size_t)k * (Pn * 2) + 2 * c]     = v;
        g_W2T[(size_t)k * (Pn * 2) + 2 * c + 1] = v;
    }
}

// ---------------- main persistent kernel -----------------------------------
__global__ __launch_bounds__(NTHR, 1)
void rtmg_main(const float* __restrict__ text,
               const float* __restrict__ prev0,
               const float* __restrict__ h0,
               const float* __restrict__ b_ih,
               const float* __restrict__ b_hh,
               const float* __restrict__ b1,
               const float* __restrict__ b2,
               float* __restrict__ out_poses,
               float* __restrict__ out_h,
               int steps)
{
    extern __shared__ float sm[];
    float* bufA   = sm;                    // h ping
    float* bufB   = bufA + Hn * SSTR;      // r / h pong
    float* bufC   = bufB + Hn * SSTR;      // text (init) / z / MLP hidden m
    float* sh_p   = bufC + Hn * SSTR;      // [72][SSTR] pose (k-major)
    float* sh_bhn = sh_p + Pn * SSTR;      // b_hh[512..767]  (n gate)
    float* sh_b1  = sh_bhn + 256;          // [256]
    float* sh_b2  = sh_b1 + MLPn;          // [72]

    const int tid     = threadIdx.x;
    const int rowbase = blockIdx.x * BM;

    for (int i = tid; i < 256;  i += NTHR) sh_bhn[i] = b_hh[512 + i];
    for (int i = tid; i < MLPn; i += NTHR) sh_b1[i] = b1[i];
    for (int i = tid; i < Pn;   i += NTHR) sh_b2[i] = b2[i];

    // stage h (k-major) into bufA, text into bufC, pose into sh_p (exact fit)
    for (int i = tid; i < Hn * BM; i += NTHR) {
        int r = i & 63, k = i >> 6;
        size_t g = (size_t)(rowbase + r);
        bufA[k * SSTR + r] = h0[g * Hn + k];
        bufC[k * SSTR + r] = text[g * Hn + k];
    }
    for (int i = tid; i < Pn * BM; i += NTHR) {
        int r = i & 63, k = i >> 6;
        sh_p[k * SSTR + r] = prev0[(size_t)(rowbase + r) * Pn + k];
    }
    __syncthreads();

    const int ct = tid & 63;          // 64 col-threads
    const int rt = tid >> 6;          // 8 row-threads
    const int r0 = rt * 8;            // 8 rows = 4 pairs = 2 quads (16B aligned)

    float* gi_blk = g_giT + (size_t)blockIdx.x * G3 * BM;
    const float* WihP = g_WihT + (size_t)Hn * (G3 * 2);   // pose rows of W_ih (dup)

    // ---- precompute gi = text@WihT + b_ih (+ b_hh folded for r,z cols) ----
    #pragma unroll 1
    for (int g = 0; g < 3; ++g) {
        const int colA = g * 256 + (ct << 1);
        const int colB = colA + 128;
        ULL aA[4][2], aB[4][2];
        #pragma unroll
        for (int c = 0; c < 2; ++c) {
            float bA = b_ih[colA + c] + ((colA + c < 512) ? b_hh[colA + c] : 0.f);
            float bB = b_ih[colB + c] + ((colB + c < 512) ? b_hh[colB + c] : 0.f);
            ULL pA = pack2(bA, bA), pB = pack2(bB, bB);
            #pragma unroll
            for (int j = 0; j < 4; ++j) { aA[j][c] = pA; aB[j][c] = pB; }
        }
        gemm_dual<Hn, G3 * 2>(aA, aB, bufC, r0, g_WihT + 2 * colA, g_WihT + 2 * colB);
        #pragma unroll
        for (int c = 0; c < 2; ++c) {
            ULL* dA = reinterpret_cast<ULL*>(gi_blk + (size_t)(colA + c) * BM + r0);
            ULL* dB = reinterpret_cast<ULL*>(gi_blk + (size_t)(colB + c) * BM + r0);
            #pragma unroll
            for (int j = 0; j < 4; ++j) { dA[j] = aA[j][c]; dB[j] = aB[j][c]; }
        }
    }
    __syncthreads();   // bufC free

    // MLP2 layout: 36 col-threads x 2 cols; 8 row-threads x 8 rows
    const int  ct2  = tid % 36;
    const int  rt2  = tid / 36;
    const bool act2 = (rt2 < 8);
    const int  c0   = ct2 * 2;
    const int  r0b  = rt2 * 8;

    float* hbuf = bufA;
    float* rbuf = bufB;
    float* zbuf = bufC;

    #pragma unroll 1
    for (int t = 0; t < steps; ++t) {
        // ---- pass 1: r & z gates fused (gi holds b_ih + b_hh already) ----
        #pragma unroll 1
        for (int ch = 0; ch < 2; ++ch) {
            const int colR = ch * 128 + (ct << 1);   // 0..255 (H space)
            const int colZ = 256 + colR;
            ULL aR[4][2], aZ[4][2];
            #pragma unroll
            for (int c = 0; c < 2; ++c) {
                const ulonglong2* gR = reinterpret_cast<const ulonglong2*>(gi_blk + (size_t)(colR + c) * BM + r0);
                const ulonglong2* gZ = reinterpret_cast<const ulonglong2*>(gi_blk + (size_t)(colZ + c) * BM + r0);
                ulonglong2 x0 = gR[0], x1 = gR[1];
                aR[0][c] = x0.x; aR[1][c] = x0.y; aR[2][c] = x1.x; aR[3][c] = x1.y;
                ulonglong2 y0 = gZ[0], y1 = gZ[1];
                aZ[0][c] = y0.x; aZ[1][c] = y0.y; aZ[2][c] = y1.x; aZ[3][c] = y1.y;
            }
            gemm_dual<Pn, G3 * 2>(aR, aZ, sh_p, r0, WihP + 2 * colR, WihP + 2 * colZ);
            gemm_dual<Hn, G3 * 2>(aR, aZ, hbuf, r0, g_WhhT + 2 * colR, g_WhhT + 2 * colZ);
            #pragma unroll
            for (int c = 0; c < 2; ++c) {
                float v[8], w[8];
                #pragma unroll
                for (int j = 0; j < 4; ++j) {
                    unpack2(aR[j][c], v[2 * j], v[2 * j + 1]);
                    unpack2(aZ[j][c], w[2 * j], w[2 * j + 1]);
                }
                float* pr = rbuf + (colR + c) * SSTR + r0;
                float* pz = zbuf + (colR + c) * SSTR + r0;
                *reinterpret_cast<float4*>(pr)     = make_float4(fsigmoid(v[0]), fsigmoid(v[1]), fsigmoid(v[2]), fsigmoid(v[3]));
                *reinterpret_cast<float4*>(pr + 4) = make_float4(fsigmoid(v[4]), fsigmoid(v[5]), fsigmoid(v[6]), fsigmoid(v[7]));
                *reinterpret_cast<float4*>(pz)     = make_float4(fsigmoid(w[0]), fsigmoid(w[1]), fsigmoid(w[2]), fsigmoid(w[3]));
                *reinterpret_cast<float4*>(pz + 4) = make_float4(fsigmoid(w[4]), fsigmoid(w[5]), fsigmoid(w[6]), fsigmoid(w[7]));
            }
        }
        __syncthreads();

        // ---- pass 2: n gate (both halves fused) + h update ----
        {
            const int colA = (ct << 1);       // 0..127
            const int colB = colA + 128;      // 128..255
            ULL giA[4][2], giB[4][2], ghA[4][2], ghB[4][2];
            #pragma unroll
            for (int c = 0; c < 2; ++c) {
                const ulonglong2* gA = reinterpret_cast<const ulonglong2*>(gi_blk + (size_t)(512 + colA + c) * BM + r0);
                const ulonglong2* gB = reinterpret_cast<const ulonglong2*>(gi_blk + (size_t)(512 + colB + c) * BM + r0);
                ulonglong2 x0 = gA[0], x1 = gA[1];
                giA[0][c] = x0.x; giA[1][c] = x0.y; giA[2][c] = x1.x; giA[3][c] = x1.y;
                ulonglong2 y0 = gB[0], y1 = gB[1];
                giB[0][c] = y0.x; giB[1][c] = y0.y; giB[2][c] = y1.x; giB[3][c] = y1.y;
                float bA = sh_bhn[colA + c], bB = sh_bhn[colB + c];
                ULL pA = pack2(bA, bA), pB = pack2(bB, bB);
                #pragma unroll
                for (int j = 0; j < 4; ++j) { ghA[j][c] = pA; ghB[j][c] = pB; }
            }
            gemm_dual<Pn, G3 * 2>(giA, giB, sh_p, r0, WihP + 2 * (512 + colA), WihP + 2 * (512 + colB));
            gemm_dual<Hn, G3 * 2>(ghA, ghB, hbuf, r0, g_WhhT + 2 * (512 + colA), g_WhhT + 2 * (512 + colB));
            #pragma unroll
            for (int half = 0; half < 2; ++half) {
                const int base = half ? colB : colA;
                #pragma unroll
                for (int c = 0; c < 2; ++c) {
                    const int o = (base + c) * SSTR + r0;
                    const float4 rv0 = *reinterpret_cast<const float4*>(rbuf + o);
                    const float4 rv1 = *reinterpret_cast<const float4*>(rbuf + o + 4);
                    const float4 zv0 = *reinterpret_cast<const float4*>(zbuf + o);
                    const float4 zv1 = *reinterpret_cast<const float4*>(zbuf + o + 4);
                    const float4 hv0 = *reinterpret_cast<const float4*>(hbuf + o);
                    const float4 hv1 = *reinterpret_cast<const float4*>(hbuf + o + 4);
                    float rr[8] = {rv0.x, rv0.y, rv0.z, rv0.w, rv1.x, rv1.y, rv1.z, rv1.w};
                    float zz[8] = {zv0.x, zv0.y, zv0.z, zv0.w, zv1.x, zv1.y, zv1.z, zv1.w};
                    float hh[8] = {hv0.x, hv0.y, hv0.z, hv0.w, hv1.x, hv1.y, hv1.z, hv1.w};
                    float on[8];
                    #pragma unroll
                    for (int j = 0; j < 4; ++j) {
                        float gil, gih, ghl, ghh;
                        if (half) { unpack2(giB[j][c], gil, gih); unpack2(ghB[j][c], ghl, ghh); }
                        else      { unpack2(giA[j][c], gil, gih); unpack2(ghA[j][c], ghl, ghh); }
                        float nl = ftanh(gil + rr[2 * j]     * ghl);
                        float nh = ftanh(gih + rr[2 * j + 1] * ghh);
                        on[2 * j]     = nl + zz[2 * j]     * (hh[2 * j]     - nl);
                        on[2 * j + 1] = nh + zz[2 * j + 1] * (hh[2 * j + 1] - nh);
                    }
                    *reinterpret_cast<float4*>(rbuf + o)     = make_float4(on[0], on[1], on[2], on[3]);
                    *reinterpret_cast<float4*>(rbuf + o + 4) = make_float4(on[4], on[5], on[6], on[7]);
                }
            }
        }
        __syncthreads();
        { float* tb = hbuf; hbuf = rbuf; rbuf = tb; }   // h_next -> hbuf

        // ---- MLP layer 1 (both halves fused): m = relu(h@W1T + b1) -> zbuf ----
        {
            const int colA = (ct << 1);
            const int colB = colA + 128;
            ULL aA[4][2], aB[4][2];
            #pragma unroll
            for (int c = 0; c < 2; ++c) {
                float bA = sh_b1[colA + c], bB = sh_b1[colB + c];
                ULL pA = pack2(bA, bA), pB = pack2(bB, bB);
                #pragma unroll
                for (int j = 0; j < 4; ++j) { aA[j][c] = pA; aB[j][c] = pB; }
            }
            gemm_dual<Hn, MLPn * 2>(aA, aB, hbuf, r0, g_W1T + 2 * colA, g_W1T + 2 * colB);
            #pragma unroll
            for (int c = 0; c < 2; ++c) {
                float v[8], w[8];
                #pragma unroll
                for (int j = 0; j < 4; ++j) {
                    unpack2(aA[j][c], v[2 * j], v[2 * j + 1]);
                    unpack2(aB[j][c], w[2 * j], w[2 * j + 1]);
                }
                float* pA = zbuf + (colA + c) * SSTR + r0;
                float* pB = zbuf + (colB + c) * SSTR + r0;
                *reinterpret_cast<float4*>(pA)     = make_float4(fmaxf(v[0], 0.f), fmaxf(v[1], 0.f), fmaxf(v[2], 0.f), fmaxf(v[3], 0.f));
                *reinterpret_cast<float4*>(pA + 4) = make_float4(fmaxf(v[4], 0.f), fmaxf(v[5], 0.f), fmaxf(v[6], 0.f), fmaxf(v[7], 0.f));
                *reinterpret_cast<float4*>(pB)     = make_float4(fmaxf(w[0], 0.f), fmaxf(w[1], 0.f), fmaxf(w[2], 0.f), fmaxf(w[3], 0.f));
                *reinterpret_cast<float4*>(pB + 4) = make_float4(fmaxf(w[4], 0.f), fmaxf(w[5], 0.f), fmaxf(w[6], 0.f), fmaxf(w[7], 0.f));
            }
        }
        __syncthreads();

        // ---- MLP layer 2: delta = m@W2T + b2; pose += delta; emit ----
        if (act2) {
            ULL acc[4][2];
            #pragma unroll
            for (int c = 0; c < 2; ++c) {
                float bv = sh_b2[c0 + c];
                ULL bb = pack2(bv, bv);
                #pragma unroll
                for (int j = 0; j < 4; ++j) acc[j][c] = bb;
            }
            gemm_one<MLPn, Pn * 2>(acc, zbuf, r0b, g_W2T + 2 * c0);
            #pragma unroll
            for (int j = 0; j < 4; ++j) {
                float d0l, d0h, d1l, d1h;
                unpack2(acc[j][0], d0l, d0h);
                unpack2(acc[j][1], d1l, d1h);
                float* p0 = sh_p + c0 * SSTR + r0b + 2 * j;
                float* p1 = sh_p + (c0 + 1) * SSTR + r0b + 2 * j;
                float a0l = p0[0] + d0l, a0h = p0[1] + d0h;
                float a1l = p1[0] + d1l, a1h = p1[1] + d1h;
                *reinterpret_cast<ULL*>(p0) = pack2(a0l, a0h);
                *reinterpret_cast<ULL*>(p1) = pack2(a1l, a1h);
                const size_t gr = (size_t)(rowbase + r0b + 2 * j);
                *reinterpret_cast<ULL*>(out_poses + (gr * steps + t) * Pn + c0)       = pack2(a0l, a1l);
                *reinterpret_cast<ULL*>(out_poses + ((gr + 1) * steps + t) * Pn + c0) = pack2(a0h, a1h);
            }
        }
        __syncthreads();
    }

    // ---- final hidden state ----
    if (out_h != nullptr) {
        for (int i = tid; i < Hn * BM; i += NTHR) {
            int r = i & 63, k = i >> 6;
            out_h[(size_t)(rowbase + r) * Hn + k] = hbuf[k * SSTR + r];
        }
    }
}

// ---------------- launch -----------------------------------------------------
extern "C" void kernel_launch(void* const* d_in, const int* in_sizes, int n_in,
                              void* d_out, int out_size)
{
    const float* text  = (const float*)d_in[0];
    const float* prev0 = (const float*)d_in[1];
    const float* h0    = (const float*)d_in[2];
    const int wi = (n_in >= 12 && in_sizes[3] == 1) ? 4 : 3;
    const float* W_ih = (const float*)d_in[wi + 0];
    const float* W_hh = (const float*)d_in[wi + 1];
    const float* b_ih = (const float*)d_in[wi + 2];
    const float* b_hh = (const float*)d_in[wi + 3];
    const float* W1   = (const float*)d_in[wi + 4];
    const float* b1   = (const float*)d_in[wi + 5];
    const float* W2   = (const float*)d_in[wi + 6];
    const float* b2   = (const float*)d_in[wi + 7];

    long long os = (long long)out_size;
    const long long PB = (long long)Bn * Pn;       // 589824
    const long long HB = (long long)Bn * Hn;       // 2097152
    int steps;
    bool has_h;
    if (os % PB == 0) { steps = (int)(os / PB); has_h = false; }
    else              { steps = (int)((os - HB) / PB); has_h = true; }
    if (steps <= 0) { steps = 64; has_h = (os > (long long)Bn * 64 * Pn); }

    float* out_poses = (float*)d_out;
    float* out_h = has_h ? out_poses + (size_t)Bn * steps * Pn : nullptr;

    const size_t smem = (size_t)(3 * Hn * SSTR + Pn * SSTR + 256 + MLPn + Pn) * sizeof(float);
    cudaFuncSetAttribute(rtmg_main, cudaFuncAttributeMaxDynamicSharedMemorySize, (int)smem);

    rtmg_prep<<<256, 256>>>(W_ih, W_hh, W1, W2);
    rtmg_main<<<NBLK, NTHR, smem>>>(text, prev0, h0, b_ih, b_hh, b1, b2,
                                    out_poses, out_h, steps);
}